// round 5
// baseline (speedup 1.0000x reference)
#include <cuda_runtime.h>
#include <cstdint>

// Problem constants
#define T_ 1024
#define K_ 2
#define E_ 8
#define H_ 2048
#define I_ 1024

#define BM 128
#define KC 32            // K chunk (tf32 elements)
#define KP 33            // padded row stride in words
#define THREADS 256
#define MAX_TILES 24

// Scratch (device globals — allocation is forbidden)
__device__ int   g_pair_src[T_ * K_];
__device__ int   g_tile_e[MAX_TILES];
__device__ int   g_tile_start[MAX_TILES];
__device__ int   g_tile_cnt[MAX_TILES];
__device__ int   g_num_tiles;
__device__ float g_inter[(size_t)T_ * K_ * I_];   // 8 MB fp32 intermediate

// ---------------------------------------------------------------- helpers
__device__ __forceinline__ uint32_t f2tf32(float f) {
    uint32_t r; asm("cvt.rna.tf32.f32 %0, %1;" : "=r"(r) : "f"(f)); return r;
}

__device__ __forceinline__ void mma_tf32(float* c, const uint32_t* a, const uint32_t* b) {
    asm volatile(
        "mma.sync.aligned.m16n8k8.row.col.f32.tf32.tf32.f32 "
        "{%0,%1,%2,%3}, {%4,%5,%6,%7}, {%8,%9}, {%0,%1,%2,%3};"
        : "+f"(c[0]), "+f"(c[1]), "+f"(c[2]), "+f"(c[3])
        : "r"(a[0]), "r"(a[1]), "r"(a[2]), "r"(a[3]), "r"(b[0]), "r"(b[1]));
}

__device__ __forceinline__ float silu(float x) {
    return x / (1.f + __expf(-x));
}

__device__ __forceinline__ float4 ldg4(const float* p) {
    return __ldg((const float4*)p);
}

// ---------------------------------------------------------------- routing
__global__ void route_kernel(const int* __restrict__ sel) {
    __shared__ int cnt[E_], cur[E_];
    int tid = threadIdx.x;
    if (tid < E_) cnt[tid] = 0;
    __syncthreads();
    for (int i = tid; i < T_ * K_; i += blockDim.x) {
        int e = min(max(sel[i], 0), E_ - 1);
        atomicAdd(&cnt[e], 1);
    }
    __syncthreads();
    if (tid == 0) {
        int off = 0, nt = 0;
        for (int e = 0; e < E_; e++) {
            cur[e] = off;
            for (int m = 0; m < cnt[e] && nt < MAX_TILES; m += BM) {
                g_tile_e[nt] = e;
                g_tile_start[nt] = off + m;
                g_tile_cnt[nt] = min(BM, cnt[e] - m);
                nt++;
            }
            off += cnt[e];
        }
        g_num_tiles = nt;
    }
    __syncthreads();
    for (int i = tid; i < T_ * K_; i += blockDim.x) {
        int e = min(max(sel[i], 0), E_ - 1);
        int pos = atomicAdd(&cur[e], 1);
        if (pos < T_ * K_) g_pair_src[pos] = i;   // i = t*K + slot; output row == i
    }
}

// ---------------------------------------------------------------- GEMM1
// inter[pair, n] = silu(x.Wg^T[n]) * (x.Wu^T[n]); CTA: 128 pairs x 64 n-cols.
// C tile 128x128: cols 0..63 = gate(nblk*64..), cols 64..127 = up(same).
// Warps 4x2: wm = rows 32*wm.., wn covers gate cols wn*32.. and up cols 64+wn*32..
__global__ void __launch_bounds__(THREADS, 1)
gemm1_kernel(const float* __restrict__ hs, const float* __restrict__ wgu) {
    const int tile = blockIdx.x;
    if (tile >= g_num_tiles) return;
    const int nblk = blockIdx.y;                 // 0..15  (I/64)
    const int e     = g_tile_e[tile];
    const int start = g_tile_start[tile];
    const int cnt   = g_tile_cnt[tile];
    const int tid = threadIdx.x, wid = tid >> 5, lane = tid & 31;
    const int wm = wid & 3, wn = wid >> 2;
    const int g = lane >> 2, t = lane & 3;

    __shared__ uint32_t As[BM][KP];
    __shared__ uint32_t Bs[BM][KP];
    __shared__ int s_tok[BM];

    if (tid < BM) {
        int v = (tid < cnt) ? g_pair_src[start + tid] : 0;
        s_tok[tid] = v / K_;
    }
    __syncthreads();

    const float* wb = wgu + (size_t)e * (2 * I_) * H_;
    const int srow = tid >> 3, sc4 = tid & 7;    // 32 rows x 8 float4 per pass

    float acc[2][8][4];
#pragma unroll
    for (int mb = 0; mb < 2; mb++)
#pragma unroll
        for (int nb = 0; nb < 8; nb++)
#pragma unroll
            for (int i = 0; i < 4; i++) acc[mb][nb][i] = 0.f;

    float4 ra[4], rb[4];
    // prefetch chunk 0 into registers
#pragma unroll
    for (int j = 0; j < 4; j++) {
        int r = srow + j * 32;
        ra[j] = (r < cnt) ? ldg4(hs + (size_t)s_tok[r] * H_ + sc4 * 4)
                          : make_float4(0.f, 0.f, 0.f, 0.f);
        int wr = (r < 64) ? (nblk * 64 + r) : (I_ + nblk * 64 + r - 64);
        rb[j] = ldg4(wb + (size_t)wr * H_ + sc4 * 4);
    }

    const int NK = H_ / KC;
#pragma unroll 1
    for (int kk = 0; kk < NK; kk++) {
        // store prefetched chunk to smem (tf32-rounded)
#pragma unroll
        for (int j = 0; j < 4; j++) {
            int r = srow + j * 32;
            As[r][sc4 * 4 + 0] = f2tf32(ra[j].x);
            As[r][sc4 * 4 + 1] = f2tf32(ra[j].y);
            As[r][sc4 * 4 + 2] = f2tf32(ra[j].z);
            As[r][sc4 * 4 + 3] = f2tf32(ra[j].w);
            Bs[r][sc4 * 4 + 0] = f2tf32(rb[j].x);
            Bs[r][sc4 * 4 + 1] = f2tf32(rb[j].y);
            Bs[r][sc4 * 4 + 2] = f2tf32(rb[j].z);
            Bs[r][sc4 * 4 + 3] = f2tf32(rb[j].w);
        }
        __syncthreads();

        // prefetch next chunk into registers (overlaps with mma below)
        if (kk + 1 < NK) {
            const int ko = (kk + 1) * KC;
#pragma unroll
            for (int j = 0; j < 4; j++) {
                int r = srow + j * 32;
                ra[j] = (r < cnt) ? ldg4(hs + (size_t)s_tok[r] * H_ + ko + sc4 * 4)
                                  : make_float4(0.f, 0.f, 0.f, 0.f);
                int wr = (r < 64) ? (nblk * 64 + r) : (I_ + nblk * 64 + r - 64);
                rb[j] = ldg4(wb + (size_t)wr * H_ + ko + sc4 * 4);
            }
        }

        // compute chunk from smem
#pragma unroll
        for (int ks = 0; ks < 4; ks++) {
            const int k0 = ks * 8;
            uint32_t af[2][4];
#pragma unroll
            for (int mb = 0; mb < 2; mb++) {
                int r = wm * 32 + mb * 16 + g;
                af[mb][0] = As[r][k0 + t];
                af[mb][1] = As[r + 8][k0 + t];
                af[mb][2] = As[r][k0 + t + 4];
                af[mb][3] = As[r + 8][k0 + t + 4];
            }
            uint32_t bf[8][2];
#pragma unroll
            for (int nb = 0; nb < 8; nb++) {
                int cb = (nb < 4) ? (wn * 32 + nb * 8) : (64 + wn * 32 + (nb - 4) * 8);
                bf[nb][0] = Bs[cb + g][k0 + t];
                bf[nb][1] = Bs[cb + g][k0 + t + 4];
            }
#pragma unroll
            for (int mb = 0; mb < 2; mb++)
#pragma unroll
                for (int nb = 0; nb < 8; nb++)
                    mma_tf32(acc[mb][nb], af[mb], bf[nb]);
        }
        __syncthreads();
    }

    // epilogue: silu(gate)*up -> g_inter
#pragma unroll
    for (int mb = 0; mb < 2; mb++) {
        int r0 = wm * 32 + mb * 16 + g;
#pragma unroll
        for (int nb = 0; nb < 4; nb++) {
            int col = nblk * 64 + wn * 32 + nb * 8 + 2 * t;
            const float* cg = acc[mb][nb];
            const float* cu = acc[mb][nb + 4];
            if (r0 < cnt) {
                float2 v = make_float2(silu(cg[0]) * cu[0], silu(cg[1]) * cu[1]);
                *(float2*)(g_inter + (size_t)(start + r0) * I_ + col) = v;
            }
            if (r0 + 8 < cnt) {
                float2 v = make_float2(silu(cg[2]) * cu[2], silu(cg[3]) * cu[3]);
                *(float2*)(g_inter + (size_t)(start + r0 + 8) * I_ + col) = v;
            }
        }
    }
}

// ---------------------------------------------------------------- GEMM2
// out[src(pair), h] = inter[pair, :] . down[e, h, :]; CTA: 128 pairs x 128 h.
__global__ void __launch_bounds__(THREADS, 1)
gemm2_kernel(const float* __restrict__ dn, float* __restrict__ out) {
    const int tile = blockIdx.x;
    if (tile >= g_num_tiles) return;
    const int nblk = blockIdx.y;                 // 0..15  (H/128)
    const int e     = g_tile_e[tile];
    const int start = g_tile_start[tile];
    const int cnt   = g_tile_cnt[tile];
    const int tid = threadIdx.x, wid = tid >> 5, lane = tid & 31;
    const int wm = wid & 3, wn = wid >> 2;
    const int g = lane >> 2, t = lane & 3;

    __shared__ uint32_t As[BM][KP];
    __shared__ uint32_t Bs[BM][KP];
    __shared__ int s_src[BM];

    if (tid < BM)
        s_src[tid] = (tid < cnt) ? g_pair_src[start + tid] : 0;
    __syncthreads();

    const float* wb = dn + ((size_t)e * H_ + (size_t)nblk * 128) * I_;
    const int srow = tid >> 3, sc4 = tid & 7;

    float acc[2][8][4];
#pragma unroll
    for (int mb = 0; mb < 2; mb++)
#pragma unroll
        for (int nb = 0; nb < 8; nb++)
#pragma unroll
            for (int i = 0; i < 4; i++) acc[mb][nb][i] = 0.f;

    float4 ra[4], rb[4];
#pragma unroll
    for (int j = 0; j < 4; j++) {
        int r = srow + j * 32;
        ra[j] = (r < cnt) ? ldg4(g_inter + (size_t)(start + r) * I_ + sc4 * 4)
                          : make_float4(0.f, 0.f, 0.f, 0.f);
        rb[j] = ldg4(wb + (size_t)r * I_ + sc4 * 4);
    }

    const int NK = I_ / KC;
#pragma unroll 1
    for (int kk = 0; kk < NK; kk++) {
#pragma unroll
        for (int j = 0; j < 4; j++) {
            int r = srow + j * 32;
            As[r][sc4 * 4 + 0] = f2tf32(ra[j].x);
            As[r][sc4 * 4 + 1] = f2tf32(ra[j].y);
            As[r][sc4 * 4 + 2] = f2tf32(ra[j].z);
            As[r][sc4 * 4 + 3] = f2tf32(ra[j].w);
            Bs[r][sc4 * 4 + 0] = f2tf32(rb[j].x);
            Bs[r][sc4 * 4 + 1] = f2tf32(rb[j].y);
            Bs[r][sc4 * 4 + 2] = f2tf32(rb[j].z);
            Bs[r][sc4 * 4 + 3] = f2tf32(rb[j].w);
        }
        __syncthreads();

        if (kk + 1 < NK) {
            const int ko = (kk + 1) * KC;
#pragma unroll
            for (int j = 0; j < 4; j++) {
                int r = srow + j * 32;
                ra[j] = (r < cnt) ? ldg4(g_inter + (size_t)(start + r) * I_ + ko + sc4 * 4)
                                  : make_float4(0.f, 0.f, 0.f, 0.f);
                rb[j] = ldg4(wb + (size_t)r * I_ + ko + sc4 * 4);
            }
        }

#pragma unroll
        for (int ks = 0; ks < 4; ks++) {
            const int k0 = ks * 8;
            uint32_t af[2][4];
#pragma unroll
            for (int mb = 0; mb < 2; mb++) {
                int r = wm * 32 + mb * 16 + g;
                af[mb][0] = As[r][k0 + t];
                af[mb][1] = As[r + 8][k0 + t];
                af[mb][2] = As[r][k0 + t + 4];
                af[mb][3] = As[r + 8][k0 + t + 4];
            }
            uint32_t bf[8][2];
#pragma unroll
            for (int nb = 0; nb < 8; nb++) {
                int cb = wn * 64 + nb * 8;
                bf[nb][0] = Bs[cb + g][k0 + t];
                bf[nb][1] = Bs[cb + g][k0 + t + 4];
            }
#pragma unroll
            for (int mb = 0; mb < 2; mb++)
#pragma unroll
                for (int nb = 0; nb < 8; nb++)
                    mma_tf32(acc[mb][nb], af[mb], bf[nb]);
        }
        __syncthreads();
    }

    // epilogue: scatter rows to out[src]
#pragma unroll
    for (int mb = 0; mb < 2; mb++) {
        int r0 = wm * 32 + mb * 16 + g;
        int src0 = s_src[r0 & (BM - 1)];
        int src1 = s_src[(r0 + 8) & (BM - 1)];
#pragma unroll
        for (int nb = 0; nb < 8; nb++) {
            int col = nblk * 128 + wn * 64 + nb * 8 + 2 * t;
            const float* c = acc[mb][nb];
            if (r0 < cnt)
                *(float2*)(out + (size_t)src0 * H_ + col) = make_float2(c[0], c[1]);
            if (r0 + 8 < cnt)
                *(float2*)(out + (size_t)src1 * H_ + col) = make_float2(c[2], c[3]);
        }
    }
}

// ---------------------------------------------------------------- launch
extern "C" void kernel_launch(void* const* d_in, const int* in_sizes, int n_in,
                              void* d_out, int out_size) {
    // Identify inputs by element count (robust to metadata ordering):
    //   hidden_states: T*H     = 2,097,152 f32
    //   selected:      T*K     = 2,048 i32
    //   gate_up_proj:  E*2I*H  = 33,554,432 f32
    //   down_proj:     E*H*I   = 16,777,216 f32
    const float* hs  = nullptr;
    const int*   sel = nullptr;
    const float* wgu = nullptr;
    const float* dn  = nullptr;
    for (int i = 0; i < n_in; i++) {
        long long n = in_sizes[i];
        if (n == (long long)T_ * H_)               hs  = (const float*)d_in[i];
        else if (n == (long long)T_ * K_)          sel = (const int*)d_in[i];
        else if (n == (long long)E_ * 2 * I_ * H_) wgu = (const float*)d_in[i];
        else if (n == (long long)E_ * H_ * I_)     dn  = (const float*)d_in[i];
    }
    float* out = (float*)d_out;
    if (!hs || !sel || !wgu || !dn) return;

    route_kernel<<<1, 256>>>(sel);
    gemm1_kernel<<<dim3(MAX_TILES, I_ / 64), THREADS>>>(hs, wgu);
    gemm2_kernel<<<dim3(MAX_TILES, H_ / 128), THREADS>>>(dn, out);
}

// round 6
// speedup vs baseline: 1.7792x; 1.7792x over previous
#include <cuda_runtime.h>
#include <cstdint>

// Problem constants
#define T_ 1024
#define K_ 2
#define E_ 8
#define H_ 2048
#define I_ 1024

#define BM 128
#define KC 32            // K chunk (tf32 elements)
#define KP 36            // padded row stride in words: bank = (4r + c) mod 32 -> conflict-free
#define THREADS 256
#define MAX_TILES 24

// Scratch (device globals — allocation is forbidden)
__device__ int   g_pair_src[T_ * K_];
__device__ int   g_tile_e[MAX_TILES];
__device__ int   g_tile_start[MAX_TILES];
__device__ int   g_tile_cnt[MAX_TILES];
__device__ int   g_num_tiles;
__device__ float g_inter[(size_t)T_ * K_ * I_];   // 8 MB fp32 intermediate

// ---------------------------------------------------------------- helpers
__device__ __forceinline__ uint32_t f2tf32(float f) {
    uint32_t r; asm("cvt.rna.tf32.f32 %0, %1;" : "=r"(r) : "f"(f)); return r;
}
__device__ __forceinline__ uint4 q2tf32(float4 v) {
    return make_uint4(f2tf32(v.x), f2tf32(v.y), f2tf32(v.z), f2tf32(v.w));
}

__device__ __forceinline__ void mma_tf32(float* c, const uint32_t* a, const uint32_t* b) {
    asm volatile(
        "mma.sync.aligned.m16n8k8.row.col.f32.tf32.tf32.f32 "
        "{%0,%1,%2,%3}, {%4,%5,%6,%7}, {%8,%9}, {%0,%1,%2,%3};"
        : "+f"(c[0]), "+f"(c[1]), "+f"(c[2]), "+f"(c[3])
        : "r"(a[0]), "r"(a[1]), "r"(a[2]), "r"(a[3]), "r"(b[0]), "r"(b[1]));
}

__device__ __forceinline__ float silu(float x) {
    return x / (1.f + __expf(-x));
}

__device__ __forceinline__ float4 ldg4(const float* p) {
    return __ldg((const float4*)p);
}

// ---------------------------------------------------------------- routing
__global__ void route_kernel(const int* __restrict__ sel) {
    __shared__ int cnt[E_], cur[E_];
    int tid = threadIdx.x;
    if (tid < E_) cnt[tid] = 0;
    __syncthreads();
    for (int i = tid; i < T_ * K_; i += blockDim.x) {
        int e = min(max(sel[i], 0), E_ - 1);
        atomicAdd(&cnt[e], 1);
    }
    __syncthreads();
    if (tid == 0) {
        int off = 0, nt = 0;
        for (int e = 0; e < E_; e++) {
            cur[e] = off;
            for (int m = 0; m < cnt[e] && nt < MAX_TILES; m += BM) {
                g_tile_e[nt] = e;
                g_tile_start[nt] = off + m;
                g_tile_cnt[nt] = min(BM, cnt[e] - m);
                nt++;
            }
            off += cnt[e];
        }
        g_num_tiles = nt;
    }
    __syncthreads();
    for (int i = tid; i < T_ * K_; i += blockDim.x) {
        int e = min(max(sel[i], 0), E_ - 1);
        int pos = atomicAdd(&cur[e], 1);
        if (pos < T_ * K_) g_pair_src[pos] = i;   // i = t*K + slot; output row == i
    }
}

// ---------------------------------------------------------------- GEMM1
// inter[pair, n] = silu(x.Wg^T[n]) * (x.Wu^T[n]); CTA: 128 pairs x 64 n-cols.
// C tile 128x128: cols 0..63 = gate(nblk*64..), cols 64..127 = up(same).
__global__ void __launch_bounds__(THREADS, 1)
gemm1_kernel(const float* __restrict__ hs, const float* __restrict__ wgu) {
    const int tile = blockIdx.x;
    if (tile >= g_num_tiles) return;
    const int nblk = blockIdx.y;                 // 0..15  (I/64)
    const int e     = g_tile_e[tile];
    const int start = g_tile_start[tile];
    const int cnt   = g_tile_cnt[tile];
    const int tid = threadIdx.x, wid = tid >> 5, lane = tid & 31;
    const int wm = wid & 3, wn = wid >> 2;
    const int g = lane >> 2, t = lane & 3;

    __shared__ uint32_t As[BM][KP];
    __shared__ uint32_t Bs[BM][KP];
    __shared__ int s_tok[BM];

    if (tid < BM) {
        int v = (tid < cnt) ? g_pair_src[start + tid] : 0;
        s_tok[tid] = v / K_;
    }
    __syncthreads();

    const float* wb = wgu + (size_t)e * (2 * I_) * H_;
    const int srow = tid >> 3, sc4 = tid & 7;    // 32 rows x 8 float4 per pass

    float acc[2][8][4];
#pragma unroll
    for (int mb = 0; mb < 2; mb++)
#pragma unroll
        for (int nb = 0; nb < 8; nb++)
#pragma unroll
            for (int i = 0; i < 4; i++) acc[mb][nb][i] = 0.f;

    float4 ra[4], rb[4];
    // prefetch chunk 0 into registers
#pragma unroll
    for (int j = 0; j < 4; j++) {
        int r = srow + j * 32;
        ra[j] = (r < cnt) ? ldg4(hs + (size_t)s_tok[r] * H_ + sc4 * 4)
                          : make_float4(0.f, 0.f, 0.f, 0.f);
        int wr = (r < 64) ? (nblk * 64 + r) : (I_ + nblk * 64 + r - 64);
        rb[j] = ldg4(wb + (size_t)wr * H_ + sc4 * 4);
    }

    const int NK = H_ / KC;
#pragma unroll 1
    for (int kk = 0; kk < NK; kk++) {
        // store prefetched chunk to smem (tf32-rounded), vectorized 16B stores
#pragma unroll
        for (int j = 0; j < 4; j++) {
            int r = srow + j * 32;
            *(uint4*)&As[r][sc4 * 4] = q2tf32(ra[j]);
            *(uint4*)&Bs[r][sc4 * 4] = q2tf32(rb[j]);
        }
        __syncthreads();

        // prefetch next chunk into registers (overlaps with mma below)
        if (kk + 1 < NK) {
            const int ko = (kk + 1) * KC;
#pragma unroll
            for (int j = 0; j < 4; j++) {
                int r = srow + j * 32;
                ra[j] = (r < cnt) ? ldg4(hs + (size_t)s_tok[r] * H_ + ko + sc4 * 4)
                                  : make_float4(0.f, 0.f, 0.f, 0.f);
                int wr = (r < 64) ? (nblk * 64 + r) : (I_ + nblk * 64 + r - 64);
                rb[j] = ldg4(wb + (size_t)wr * H_ + ko + sc4 * 4);
            }
        }

        // compute chunk from smem (conflict-free: bank = 4*row + col mod 32)
#pragma unroll
        for (int ks = 0; ks < 4; ks++) {
            const int k0 = ks * 8;
            uint32_t af[2][4];
#pragma unroll
            for (int mb = 0; mb < 2; mb++) {
                int r = wm * 32 + mb * 16 + g;
                af[mb][0] = As[r][k0 + t];
                af[mb][1] = As[r + 8][k0 + t];
                af[mb][2] = As[r][k0 + t + 4];
                af[mb][3] = As[r + 8][k0 + t + 4];
            }
            uint32_t bf[8][2];
#pragma unroll
            for (int nb = 0; nb < 8; nb++) {
                int cb = (nb < 4) ? (wn * 32 + nb * 8) : (64 + wn * 32 + (nb - 4) * 8);
                bf[nb][0] = Bs[cb + g][k0 + t];
                bf[nb][1] = Bs[cb + g][k0 + t + 4];
            }
#pragma unroll
            for (int mb = 0; mb < 2; mb++)
#pragma unroll
                for (int nb = 0; nb < 8; nb++)
                    mma_tf32(acc[mb][nb], af[mb], bf[nb]);
        }
        __syncthreads();
    }

    // epilogue: silu(gate)*up -> g_inter
#pragma unroll
    for (int mb = 0; mb < 2; mb++) {
        int r0 = wm * 32 + mb * 16 + g;
#pragma unroll
        for (int nb = 0; nb < 4; nb++) {
            int col = nblk * 64 + wn * 32 + nb * 8 + 2 * t;
            const float* cg = acc[mb][nb];
            const float* cu = acc[mb][nb + 4];
            if (r0 < cnt) {
                float2 v = make_float2(silu(cg[0]) * cu[0], silu(cg[1]) * cu[1]);
                *(float2*)(g_inter + (size_t)(start + r0) * I_ + col) = v;
            }
            if (r0 + 8 < cnt) {
                float2 v = make_float2(silu(cg[2]) * cu[2], silu(cg[3]) * cu[3]);
                *(float2*)(g_inter + (size_t)(start + r0 + 8) * I_ + col) = v;
            }
        }
    }
}

// ---------------------------------------------------------------- GEMM2
// out[src(pair), h] = inter[pair, :] . down[e, h, :]; CTA: 128 pairs x 128 h.
__global__ void __launch_bounds__(THREADS, 1)
gemm2_kernel(const float* __restrict__ dn, float* __restrict__ out) {
    const int tile = blockIdx.x;
    if (tile >= g_num_tiles) return;
    const int nblk = blockIdx.y;                 // 0..15  (H/128)
    const int e     = g_tile_e[tile];
    const int start = g_tile_start[tile];
    const int cnt   = g_tile_cnt[tile];
    const int tid = threadIdx.x, wid = tid >> 5, lane = tid & 31;
    const int wm = wid & 3, wn = wid >> 2;
    const int g = lane >> 2, t = lane & 3;

    __shared__ uint32_t As[BM][KP];
    __shared__ uint32_t Bs[BM][KP];
    __shared__ int s_src[BM];

    if (tid < BM)
        s_src[tid] = (tid < cnt) ? g_pair_src[start + tid] : 0;
    __syncthreads();

    const float* wb = dn + ((size_t)e * H_ + (size_t)nblk * 128) * I_;
    const int srow = tid >> 3, sc4 = tid & 7;

    float acc[2][8][4];
#pragma unroll
    for (int mb = 0; mb < 2; mb++)
#pragma unroll
        for (int nb = 0; nb < 8; nb++)
#pragma unroll
            for (int i = 0; i < 4; i++) acc[mb][nb][i] = 0.f;

    float4 ra[4], rb[4];
#pragma unroll
    for (int j = 0; j < 4; j++) {
        int r = srow + j * 32;
        ra[j] = (r < cnt) ? ldg4(g_inter + (size_t)(start + r) * I_ + sc4 * 4)
                          : make_float4(0.f, 0.f, 0.f, 0.f);
        rb[j] = ldg4(wb + (size_t)r * I_ + sc4 * 4);
    }

    const int NK = I_ / KC;
#pragma unroll 1
    for (int kk = 0; kk < NK; kk++) {
#pragma unroll
        for (int j = 0; j < 4; j++) {
            int r = srow + j * 32;
            *(uint4*)&As[r][sc4 * 4] = q2tf32(ra[j]);
            *(uint4*)&Bs[r][sc4 * 4] = q2tf32(rb[j]);
        }
        __syncthreads();

        if (kk + 1 < NK) {
            const int ko = (kk + 1) * KC;
#pragma unroll
            for (int j = 0; j < 4; j++) {
                int r = srow + j * 32;
                ra[j] = (r < cnt) ? ldg4(g_inter + (size_t)(start + r) * I_ + ko + sc4 * 4)
                                  : make_float4(0.f, 0.f, 0.f, 0.f);
                rb[j] = ldg4(wb + (size_t)r * I_ + ko + sc4 * 4);
            }
        }

#pragma unroll
        for (int ks = 0; ks < 4; ks++) {
            const int k0 = ks * 8;
            uint32_t af[2][4];
#pragma unroll
            for (int mb = 0; mb < 2; mb++) {
                int r = wm * 32 + mb * 16 + g;
                af[mb][0] = As[r][k0 + t];
                af[mb][1] = As[r + 8][k0 + t];
                af[mb][2] = As[r][k0 + t + 4];
                af[mb][3] = As[r + 8][k0 + t + 4];
            }
            uint32_t bf[8][2];
#pragma unroll
            for (int nb = 0; nb < 8; nb++) {
                int cb = wn * 64 + nb * 8;
                bf[nb][0] = Bs[cb + g][k0 + t];
                bf[nb][1] = Bs[cb + g][k0 + t + 4];
            }
#pragma unroll
            for (int mb = 0; mb < 2; mb++)
#pragma unroll
                for (int nb = 0; nb < 8; nb++)
                    mma_tf32(acc[mb][nb], af[mb], bf[nb]);
        }
        __syncthreads();
    }

    // epilogue: scatter rows to out[src]
#pragma unroll
    for (int mb = 0; mb < 2; mb++) {
        int r0 = wm * 32 + mb * 16 + g;
        int src0 = s_src[r0 & (BM - 1)];
        int src1 = s_src[(r0 + 8) & (BM - 1)];
#pragma unroll
        for (int nb = 0; nb < 8; nb++) {
            int col = nblk * 128 + wn * 64 + nb * 8 + 2 * t;
            const float* c = acc[mb][nb];
            if (r0 < cnt)
                *(float2*)(out + (size_t)src0 * H_ + col) = make_float2(c[0], c[1]);
            if (r0 + 8 < cnt)
                *(float2*)(out + (size_t)src1 * H_ + col) = make_float2(c[2], c[3]);
        }
    }
}

// ---------------------------------------------------------------- launch
extern "C" void kernel_launch(void* const* d_in, const int* in_sizes, int n_in,
                              void* d_out, int out_size) {
    // Identify inputs by element count (robust to metadata ordering):
    //   hidden_states: T*H     = 2,097,152 f32
    //   selected:      T*K     = 2,048 i32
    //   gate_up_proj:  E*2I*H  = 33,554,432 f32
    //   down_proj:     E*H*I   = 16,777,216 f32
    const float* hs  = nullptr;
    const int*   sel = nullptr;
    const float* wgu = nullptr;
    const float* dn  = nullptr;
    for (int i = 0; i < n_in; i++) {
        long long n = in_sizes[i];
        if (n == (long long)T_ * H_)               hs  = (const float*)d_in[i];
        else if (n == (long long)T_ * K_)          sel = (const int*)d_in[i];
        else if (n == (long long)E_ * 2 * I_ * H_) wgu = (const float*)d_in[i];
        else if (n == (long long)E_ * H_ * I_)     dn  = (const float*)d_in[i];
    }
    float* out = (float*)d_out;
    if (!hs || !sel || !wgu || !dn) return;

    route_kernel<<<1, 256>>>(sel);
    gemm1_kernel<<<dim3(MAX_TILES, I_ / 64), THREADS>>>(hs, wgu);
    gemm2_kernel<<<dim3(MAX_TILES, H_ / 128), THREADS>>>(dn, out);
}